// round 14
// baseline (speedup 1.0000x reference)
#include <cuda_runtime.h>
#include <cuda_fp16.h>
#include <math.h>
#include <stdint.h>

#define B_ 2
#define S_ 2048
#define DM_ 2048
#define H_ 8
#define DH_ 128
#define INNER_ 1024
#define MROWS (B_*S_)   // 4096
#define SROWS S_        // rows per batch
#define HROWS (S_/2)    // rows per half-batch chunk

// ---------------- scratch (device globals; no allocation allowed) ----------
__device__ float g_q[MROWS * INNER_];
__device__ float g_k[MROWS * INNER_];
__device__ float g_v[MROWS * INNER_];
__device__ float g_beta[MROWS * H_];
__device__ float g_amean[H_];
__device__ float g_ctab[S_ * 64];
__device__ float g_stab[S_ * 64];

__device__ __align__(128) __half g_xh[MROWS * DM_];
__device__ __align__(128) __half g_wqh[INNER_ * DM_];
__device__ __align__(128) __half g_wkh[INNER_ * DM_];
__device__ __align__(128) __half g_wvh[INNER_ * DM_];
__device__ __align__(128) __half g_woh[DM_ * INNER_];
__device__ __align__(128) __half g_ah[MROWS * INNER_];

#define STWIN_ 128
#define STCH 4
#define STLEN (STWIN_/STCH)   // 32
__device__ float g_stpart[B_ * H_ * STCH * DH_ * DH_];

__device__ __forceinline__ float sigmoidf_(float x) {
    return 1.0f / (1.0f + expf(-x));
}

// ======================= PTX helpers ==============================
__device__ __forceinline__ uint32_t smem_u32(const void* p) {
    uint32_t a;
    asm("{ .reg .u64 t; cvta.to.shared.u64 t, %1; cvt.u32.u64 %0, t; }"
        : "=r"(a) : "l"(p));
    return a;
}

#define CP_ASYNC16(dst, src) \
    asm volatile("cp.async.cg.shared.global [%0], [%1], 16;" :: "r"(dst), "l"(src) : "memory")
#define CP_COMMIT() asm volatile("cp.async.commit_group;" ::: "memory")
#define CP_WAIT(n)  asm volatile("cp.async.wait_group %0;" :: "n"(n) : "memory")

__device__ __forceinline__ void ldsm_x4(uint32_t& r0, uint32_t& r1, uint32_t& r2, uint32_t& r3,
                                        uint32_t addr) {
    asm volatile("ldmatrix.sync.aligned.m8n8.x4.shared.b16 {%0,%1,%2,%3}, [%4];"
        : "=r"(r0), "=r"(r1), "=r"(r2), "=r"(r3) : "r"(addr));
}

__device__ __forceinline__ void mma16816(float* c, const uint32_t* a, uint32_t b0, uint32_t b1) {
    asm volatile(
        "mma.sync.aligned.m16n8k16.row.col.f32.f16.f16.f32 "
        "{%0,%1,%2,%3}, {%4,%5,%6,%7}, {%8,%9}, {%0,%1,%2,%3};"
        : "+f"(c[0]), "+f"(c[1]), "+f"(c[2]), "+f"(c[3])
        : "r"(a[0]), "r"(a[1]), "r"(a[2]), "r"(a[3]), "r"(b0), "r"(b1));
}

// ======================= prep_main: x->fp16 + weight->fp16 ==================
__global__ __launch_bounds__(256) void prep_main(
    const float* __restrict__ x,
    const float* __restrict__ Wq, const float* __restrict__ Wk,
    const float* __restrict__ Wv, const float* __restrict__ Wo,
    __half* __restrict__ xh,
    __half* __restrict__ wqh, __half* __restrict__ wkh,
    __half* __restrict__ wvh, __half* __restrict__ woh) {
    int blk = blockIdx.x;
    int tid = threadIdx.x;
    const float* s;
    __half* d;
    int i;
    if (blk < 8192) {
        s = x; d = xh;
        i = blk * 256 + tid;
    } else {
        int idx = blk - 8192;
        int seg = idx >> 11;
        s = (seg == 0) ? Wq : (seg == 1) ? Wk : (seg == 2) ? Wv : Wo;
        d = (seg == 0) ? wqh : (seg == 1) ? wkh : (seg == 2) ? wvh : woh;
        i = (idx & 2047) * 256 + tid;
    }
    float4 v = ((const float4*)s)[i];
    __half2* p = (__half2*)d;
    p[2*i]   = __half2(__float2half(v.x), __float2half(v.y));
    p[2*i+1] = __half2(__float2half(v.z), __float2half(v.w));
}

// ======================= prep_side: beta + rope table + amean ===============
#define PS_BETA MROWS
#define PS_ROPE (PS_BETA + 512)
#define PS_GRID (PS_ROPE + 1)
__global__ __launch_bounds__(256) void prep_side(
    const float* __restrict__ x,
    const float* __restrict__ Wb, const float* __restrict__ bb,
    const float* __restrict__ alpha_log,
    float* __restrict__ beta,
    float* __restrict__ ctab, float* __restrict__ stab) {
    int blk = blockIdx.x;
    int tid = threadIdx.x;
    if (blk < PS_BETA) {
        __shared__ float xs[DM_];
        int row = blk;
        const float4* src = (const float4*)(x + (size_t)row * DM_);
        for (int i = tid; i < DM_/4; i += 256)
            *(float4*)&xs[i*4] = src[i];
        __syncthreads();
        int w = tid >> 5;
        int lane = tid & 31;
        const float* wr = Wb + w * DM_;
        float sum = 0.f;
        for (int i = lane; i < DM_; i += 32)
            sum += xs[i] * wr[i];
        #pragma unroll
        for (int o = 16; o; o >>= 1) sum += __shfl_xor_sync(0xffffffffu, sum, o);
        if (lane == 0) beta[row * H_ + w] = sigmoidf_(sum + bb[w]);
    } else if (blk < PS_ROPE) {
        int idx = (blk - PS_BETA) * 256 + tid;
        int j = idx & 63;
        int s = idx >> 6;
        float ex = (float)(2 * j) * (1.0f / (float)DH_);
        float inv = powf(10000.0f, -ex);
        float sn, c;
        sincosf((float)s * inv, &sn, &c);
        ctab[idx] = c;
        stab[idx] = sn;
    } else {
        int w = tid >> 5;
        int lane = tid & 31;
        float s = 0.f;
        for (int d = lane; d < DH_; d += 32)
            s += sigmoidf_(alpha_log[w * DH_ + d]);
        #pragma unroll
        for (int o = 16; o; o >>= 1) s += __shfl_xor_sync(0xffffffffu, s, o);
        if (lane == 0) g_amean[w] = s / (float)DH_;
    }
}

// ======================= fp16 1-pass HMMA GEMM (128x64, 3 CTAs/SM) ==========
// C[M,N](fp32) = Ah[M,K] @ Bh[N,K]^T over rows [m_base, ...).
// 128x64 CTA tile, 8 warps @ 32x32, k-chunk 64 halves, 3-stage cp.async.
#define NSTG 3
#define TILE_A 16384u                   // A: 128 rows x 128B
#define TILE_BB 8192u                   // B:  64 rows x 128B
#define STG_BYTES (TILE_A + TILE_BB)    // 24KB
#define GEMM_SMEM (NSTG * STG_BYTES)    // 72KB

__global__ __launch_bounds__(256, 3) void hmma_gemm(
    const __half* __restrict__ Ah,
    const __half* __restrict__ B0, const __half* __restrict__ B1,
    const __half* __restrict__ B2,
    float* __restrict__ C0, float* __restrict__ C1, float* __restrict__ C2,
    int K, int ldc, int m_base) {
    extern __shared__ char smem[];
    uint32_t sm = smem_u32(smem);
    int tid = threadIdx.x;
    int lane = tid & 31;
    int wid = tid >> 5;
    int wm = wid & 3;          // 4 M-blocks of 32
    int wn = wid >> 2;         // 2 N-blocks of 32
    int m0 = m_base + blockIdx.y * 128;
    int n0 = blockIdx.x * 64;

    const __half* Bh;
    float* C;
    if (blockIdx.z == 0)      { Bh = B0; C = C0; }
    else if (blockIdx.z == 1) { Bh = B1; C = C1; }
    else                      { Bh = B2; C = C2; }

    int kiters = K >> 6;

    float acc[2][4][4];
    #pragma unroll
    for (int i = 0; i < 2; i++)
        #pragma unroll
        for (int j = 0; j < 4; j++)
            #pragma unroll
            for (int t = 0; t < 4; t++) acc[i][j][t] = 0.f;

    int lc = tid & 7;
    int lr = tid >> 3;

    #define ISSUE_STAGE(ip, buf) do {                                          \
        int _k0 = (ip) << 6;                                                   \
        const __half* _ah = Ah + (size_t)(m0 + lr) * K + _k0 + lc * 8;         \
        const __half* _bh = Bh + (size_t)(n0 + lr) * K + _k0 + lc * 8;         \
        uint32_t _sb = sm + (buf) * STG_BYTES;                                 \
        _Pragma("unroll")                                                      \
        for (int _i = 0; _i < 4; _i++) {                                       \
            int _row = lr + 32 * _i;                                           \
            uint32_t _sw = ((uint32_t)_row << 7) + (((uint32_t)(lc ^ (_row & 7))) << 4); \
            CP_ASYNC16(_sb + _sw, _ah + (size_t)(32 * _i) * K);                \
        }                                                                      \
        _Pragma("unroll")                                                      \
        for (int _i = 0; _i < 2; _i++) {                                       \
            int _row = lr + 32 * _i;                                           \
            uint32_t _sw = ((uint32_t)_row << 7) + (((uint32_t)(lc ^ (_row & 7))) << 4); \
            CP_ASYNC16(_sb + TILE_A + _sw, _bh + (size_t)(32 * _i) * K);       \
        }                                                                      \
    } while (0)

    ISSUE_STAGE(0, 0); CP_COMMIT();
    ISSUE_STAGE(1, 1); CP_COMMIT();

    for (int it = 0; it < kiters; ++it) {
        if (it + 1 < kiters) { CP_WAIT(1); } else { CP_WAIT(0); }
        __syncthreads();
        if (it + 2 < kiters) {
            int nb = it + 2; while (nb >= 3) nb -= 3;
            ISSUE_STAGE(it + 2, nb);
            CP_COMMIT();
        }
        int cb = it; while (cb >= 3) cb -= 3;
        uint32_t sah = sm + cb * STG_BYTES;
        uint32_t sbh = sah + TILE_A;
        #pragma unroll
        for (int ks = 0; ks < 4; ++ks) {
            int ch = ks * 2 + (lane >> 4);
            uint32_t bfr[2][4];
            #pragma unroll
            for (int nt2 = 0; nt2 < 2; ++nt2) {
                int rowB = wn * 32 + nt2 * 16 + (lane & 7) + ((lane >> 3) & 1) * 8;
                uint32_t off = ((uint32_t)rowB << 7) + (((uint32_t)(ch ^ (rowB & 7))) << 4);
                ldsm_x4(bfr[nt2][0], bfr[nt2][1], bfr[nt2][2], bfr[nt2][3], sbh + off);
            }
            #pragma unroll
            for (int mt = 0; mt < 2; ++mt) {
                int rowA = wm * 32 + mt * 16 + (lane & 7) + ((lane >> 3) & 1) * 8;
                uint32_t off = ((uint32_t)rowA << 7) + (((uint32_t)(ch ^ (rowA & 7))) << 4);
                uint32_t a[4];
                ldsm_x4(a[0], a[1], a[2], a[3], sah + off);
                #pragma unroll
                for (int nt2 = 0; nt2 < 2; ++nt2) {
                    mma16816(acc[mt][nt2 * 2 + 0], a, bfr[nt2][0], bfr[nt2][2]);
                    mma16816(acc[mt][nt2 * 2 + 1], a, bfr[nt2][1], bfr[nt2][3]);
                }
            }
        }
    }
    #undef ISSUE_STAGE

    // -------- epilogue --------
    #pragma unroll
    for (int mt = 0; mt < 2; ++mt) {
        int m = m0 + wm * 32 + mt * 16 + (lane >> 2);
        #pragma unroll
        for (int nt = 0; nt < 4; ++nt) {
            int n = n0 + wn * 32 + nt * 8 + (lane & 3) * 2;
            float* p = C + (size_t)m * ldc + n;
            *(float2*)p = make_float2(acc[mt][nt][0], acc[mt][nt][1]);
            *(float2*)(p + 8 * (size_t)ldc) = make_float2(acc[mt][nt][2], acc[mt][nt][3]);
        }
    }
}

// ---------------- smem-tiled windowed decay attention with fused RoPE ------
#define WIN_ 32
#define ATT_S 8
#define ATT_ROWS (WIN_ - 1 + ATT_S)   // 39
__global__ __launch_bounds__(256) void attn_kernel(const float* __restrict__ q,
                                                   const float* __restrict__ k,
                                                   const float* __restrict__ v,
                                                   const float* __restrict__ beta,
                                                   const float* __restrict__ ctab,
                                                   const float* __restrict__ stab,
                                                   __half* __restrict__ ah,
                                                   int b, int s_base) {
    __shared__ float ks[ATT_ROWS * DH_];
    __shared__ float vs[ATT_ROWS * DH_];
    __shared__ float bs[ATT_ROWS];
    int tid = threadIdx.x;
    int wid = tid >> 5;
    int lane = tid & 31;
    int s0 = s_base + blockIdx.x * ATT_S;
    int h  = blockIdx.y;
    int base_t = s0 - (WIN_ - 1);

    size_t bh = (size_t)b * S_ * INNER_ + h * DH_;

    for (int i = tid; i < ATT_ROWS * 32; i += 256) {
        int r = i >> 5;
        int c = (i & 31) * 4;
        int t = base_t + r;
        float4 z = make_float4(0.f, 0.f, 0.f, 0.f);
        float4 kv = z, vv = z;
        if (t >= 0) {
            kv = *(const float4*)(k + bh + (size_t)t * INNER_ + c);
            vv = *(const float4*)(v + bh + (size_t)t * INNER_ + c);
        }
        *(float4*)&ks[r * DH_ + c] = kv;
        *(float4*)&vs[r * DH_ + c] = vv;
    }
    if (tid < ATT_ROWS) {
        int t = base_t + tid;
        bs[tid] = (t >= 0) ? beta[(size_t)(b * S_ + t) * H_ + h] : 0.f;
    }
    __syncthreads();

    for (int i = tid; i < ATT_ROWS * 16; i += 256) {
        int r = i >> 4;
        int c = (i & 15) * 4;
        int t = base_t + r;
        if (t < 0) continue;
        float4 a = *(float4*)&ks[r * DH_ + c];
        float4 p = *(float4*)&ks[r * DH_ + c + 64];
        float4 ct4 = *(const float4*)&ctab[(size_t)t * 64 + c];
        float4 st4 = *(const float4*)&stab[(size_t)t * 64 + c];
        float4 lo, hi;
        lo.x = a.x*ct4.x - p.x*st4.x;  hi.x = p.x*ct4.x + a.x*st4.x;
        lo.y = a.y*ct4.y - p.y*st4.y;  hi.y = p.y*ct4.y + a.y*st4.y;
        lo.z = a.z*ct4.z - p.z*st4.z;  hi.z = p.z*ct4.z + a.z*st4.z;
        lo.w = a.w*ct4.w - p.w*st4.w;  hi.w = p.w*ct4.w + a.w*st4.w;
        *(float4*)&ks[r * DH_ + c]      = lo;
        *(float4*)&ks[r * DH_ + c + 64] = hi;
    }
    __syncthreads();

    int s = s0 + wid;
    float am = g_amean[h];
    float am2 = am * am;
    float am3 = am2 * am;
    float am4 = am2 * am2;
    int c4 = lane * 4;

    float4 qraw = *(const float4*)(q + bh + (size_t)s * INNER_ + c4);
    int jj = (lane & 15) * 4;
    float4 ct4 = *(const float4*)&ctab[(size_t)s * 64 + jj];
    float4 st4 = *(const float4*)&stab[(size_t)s * 64 + jj];
    float px = __shfl_xor_sync(0xffffffffu, qraw.x, 16);
    float py = __shfl_xor_sync(0xffffffffu, qraw.y, 16);
    float pz = __shfl_xor_sync(0xffffffffu, qraw.z, 16);
    float pw = __shfl_xor_sync(0xffffffffu, qraw.w, 16);
    float4 qv;
    if (lane < 16) {
        qv.x = qraw.x*ct4.x - px*st4.x;
        qv.y = qraw.y*ct4.y - py*st4.y;
        qv.z = qraw.z*ct4.z - pz*st4.z;
        qv.w = qraw.w*ct4.w - pw*st4.w;
    } else {
        qv.x = qraw.x*ct4.x + px*st4.x;
        qv.y = qraw.y*ct4.y + py*st4.y;
        qv.z = qraw.z*ct4.z + pz*st4.z;
        qv.w = qraw.w*ct4.w + pw*st4.w;
    }

    float4 acc = make_float4(0.f, 0.f, 0.f, 0.f);
    float decay = 1.f;
    int t_lo = s - (WIN_ - 1); if (t_lo < 0) t_lo = 0;

    for (int t4 = s; t4 >= t_lo; t4 -= 4) {
        int r0 = t4 - base_t;
        bool m1 = t4 - 1 >= t_lo, m2 = t4 - 2 >= t_lo, m3 = t4 - 3 >= t_lo;
        float4 z = make_float4(0.f, 0.f, 0.f, 0.f);
        float4 k0 = *(const float4*)&ks[r0 * DH_ + c4];
        float4 v0 = *(const float4*)&vs[r0 * DH_ + c4];
        float4 k1 = m1 ? *(const float4*)&ks[(r0-1) * DH_ + c4] : z;
        float4 v1 = m1 ? *(const float4*)&vs[(r0-1) * DH_ + c4] : z;
        float4 k2 = m2 ? *(const float4*)&ks[(r0-2) * DH_ + c4] : z;
        float4 v2 = m2 ? *(const float4*)&vs[(r0-2) * DH_ + c4] : z;
        float4 k3 = m3 ? *(const float4*)&ks[(r0-3) * DH_ + c4] : z;
        float4 v3 = m3 ? *(const float4*)&vs[(r0-3) * DH_ + c4] : z;
        float d0 = qv.x*k0.x + qv.y*k0.y + qv.z*k0.z + qv.w*k0.w;
        float d1 = qv.x*k1.x + qv.y*k1.y + qv.z*k1.z + qv.w*k1.w;
        float d2 = qv.x*k2.x + qv.y*k2.y + qv.z*k2.z + qv.w*k2.w;
        float d3 = qv.x*k3.x + qv.y*k3.y + qv.z*k3.z + qv.w*k3.w;
        #pragma unroll
        for (int o = 16; o; o >>= 1) {
            d0 += __shfl_xor_sync(0xffffffffu, d0, o);
            d1 += __shfl_xor_sync(0xffffffffu, d1, o);
            d2 += __shfl_xor_sync(0xffffffffu, d2, o);
            d3 += __shfl_xor_sync(0xffffffffu, d3, o);
        }
        float w0 = d0 * decay * bs[r0];
        float w1 = m1 ? d1 * decay * am  * bs[r0-1] : 0.f;
        float w2 = m2 ? d2 * decay * am2 * bs[r0-2] : 0.f;
        float w3 = m3 ? d3 * decay * am3 * bs[r0-3] : 0.f;
        acc.x = fmaf(w0, v0.x, fmaf(w1, v1.x, fmaf(w2, v2.x, fmaf(w3, v3.x, acc.x))));
        acc.y = fmaf(w0, v0.y, fmaf(w1, v1.y, fmaf(w2, v2.y, fmaf(w3, v3.y, acc.y))));
        acc.z = fmaf(w0, v0.z, fmaf(w1, v1.z, fmaf(w2, v2.z, fmaf(w3, v3.z, acc.z))));
        acc.w = fmaf(w0, v0.w, fmaf(w1, v1.w, fmaf(w2, v2.w, fmaf(w3, v3.w, acc.w))));
        decay *= am4;
    }
    size_t o = bh + (size_t)s * INNER_ + c4;
    ((__half2*)(ah + o))[0] = __half2(__float2half(acc.x), __float2half(acc.y));
    ((__half2*)(ah + o))[1] = __half2(__float2half(acc.z), __float2half(acc.w));
}

// ---------------- recurrent state: partial chunks + combine ----------------
__global__ __launch_bounds__(256) void state_part(const float* __restrict__ k,
                                                  const float* __restrict__ v,
                                                  const float* __restrict__ beta,
                                                  const float* __restrict__ alpha_log,
                                                  const float* __restrict__ ctab,
                                                  const float* __restrict__ stab,
                                                  float* __restrict__ part,
                                                  int b) {
    int h  = blockIdx.x >> 2;
    int c  = blockIdx.x & 3;
    int bh = b * H_ + h;
    int tid = threadIdx.x;
    int d = tid >> 1;
    int e0 = (tid & 1) * 64;
    __shared__ float ks[DH_], vs[DH_];
    float st[64];
    #pragma unroll
    for (int e = 0; e < 64; e++) st[e] = 0.f;
    float ad = sigmoidf_(alpha_log[h * DH_ + d]);
    int tbeg = S_ - STWIN_ + c * STLEN;
    for (int t = tbeg; t < tbeg + STLEN; t++) {
        __syncthreads();
        size_t base = (size_t)(b * S_ + t) * INNER_ + h * DH_;
        if (tid < 128) ks[tid] = k[base + tid];
        else           vs[tid - 128] = v[base + tid - 128];
        __syncthreads();
        float cv = ctab[(size_t)t * 64 + (d & 63)];
        float sv = stab[(size_t)t * 64 + (d & 63)];
        float kd = (d < 64) ? ks[d] * cv - ks[d + 64] * sv
                            : ks[d] * cv + ks[d - 64] * sv;
        float kb = kd * beta[(b * S_ + t) * H_ + h];
        #pragma unroll
        for (int e = 0; e < 64; e++)
            st[e] = fmaf(ad, st[e], kb * vs[e0 + e]);
    }
    float* op = part + (((size_t)bh * STCH + c) * DH_ + d) * DH_ + e0;
    #pragma unroll
    for (int e = 0; e < 64; e++) op[e] = st[e];
}

__global__ __launch_bounds__(256) void state_comb(const float* __restrict__ part,
                                                  const float* __restrict__ alpha_log,
                                                  float* __restrict__ stout) {
    int bh = blockIdx.x;
    int h = bh & 7;
    int tid = threadIdx.x;
    int d = tid >> 1;
    int e0 = (tid & 1) * 64;
    float ad = sigmoidf_(alpha_log[h * DH_ + d]);
    float a32 = ad;
    a32 *= a32; a32 *= a32; a32 *= a32; a32 *= a32; a32 *= a32;
    const float* p0 = part + (((size_t)bh * STCH + 0) * DH_ + d) * DH_ + e0;
    const float* p1 = part + (((size_t)bh * STCH + 1) * DH_ + d) * DH_ + e0;
    const float* p2 = part + (((size_t)bh * STCH + 2) * DH_ + d) * DH_ + e0;
    const float* p3 = part + (((size_t)bh * STCH + 3) * DH_ + d) * DH_ + e0;
    float* op = stout + ((size_t)bh * DH_ + d) * DH_ + e0;
    #pragma unroll
    for (int e = 0; e < 64; e++) {
        float r = p0[e];
        r = fmaf(r, a32, p1[e]);
        r = fmaf(r, a32, p2[e]);
        r = fmaf(r, a32, p3[e]);
        op[e] = r;
    }
}

// ---------------- launch ----------------
extern "C" void kernel_launch(void* const* d_in, const int* in_sizes, int n_in,
                              void* d_out, int out_size) {
    const float* x         = (const float*)d_in[0];
    const float* Wq        = (const float*)d_in[1];
    const float* Wk        = (const float*)d_in[2];
    const float* Wv        = (const float*)d_in[3];
    const float* Wo        = (const float*)d_in[4];
    const float* Wb        = (const float*)d_in[5];
    const float* bb        = (const float*)d_in[6];
    const float* alpha_log = (const float*)d_in[7];
    float* out = (float*)d_out;

    float *q, *k, *v, *beta, *stpart, *ctab, *stab;
    cudaGetSymbolAddress((void**)&q,      g_q);
    cudaGetSymbolAddress((void**)&k,      g_k);
    cudaGetSymbolAddress((void**)&v,      g_v);
    cudaGetSymbolAddress((void**)&beta,   g_beta);
    cudaGetSymbolAddress((void**)&stpart, g_stpart);
    cudaGetSymbolAddress((void**)&ctab,   g_ctab);
    cudaGetSymbolAddress((void**)&stab,   g_stab);
    __half *xh, *wqh, *wkh, *wvh, *woh, *ah;
    cudaGetSymbolAddress((void**)&xh,  g_xh);
    cudaGetSymbolAddress((void**)&wqh, g_wqh);
    cudaGetSymbolAddress((void**)&wkh, g_wkh);
    cudaGetSymbolAddress((void**)&wvh, g_wvh);
    cudaGetSymbolAddress((void**)&woh, g_woh);
    cudaGetSymbolAddress((void**)&ah,  g_ah);

    // one-time resources (host-side handles, no device memory)
    static cudaStream_t s1 = 0;
    static cudaEvent_t eQ0, eQ1, eA0a, eA0b, eA1a, eA1b, eS;
    if (!s1) {
        cudaStreamCreateWithFlags(&s1, cudaStreamNonBlocking);
        cudaEventCreateWithFlags(&eQ0,  cudaEventDisableTiming);
        cudaEventCreateWithFlags(&eQ1,  cudaEventDisableTiming);
        cudaEventCreateWithFlags(&eA0a, cudaEventDisableTiming);
        cudaEventCreateWithFlags(&eA0b, cudaEventDisableTiming);
        cudaEventCreateWithFlags(&eA1a, cudaEventDisableTiming);
        cudaEventCreateWithFlags(&eA1b, cudaEventDisableTiming);
        cudaEventCreateWithFlags(&eS,   cudaEventDisableTiming);
        cudaFuncSetAttribute(hmma_gemm, cudaFuncAttributeMaxDynamicSharedMemorySize, GEMM_SMEM);
    }

    // ---- prep: main-stream (xh + weights) ∥ side-stream (beta/rope/amean) --
    prep_main<<<16384, 256>>>(x, Wq, Wk, Wv, Wo, xh, wqh, wkh, wvh, woh);
    prep_side<<<PS_GRID, 256, 0, s1>>>(x, Wb, bb, alpha_log, beta, ctab, stab);

    // ---- QKV GEMMs, split by batch ----
    dim3 gqkv(INNER_/64, SROWS/128, 3);
    hmma_gemm<<<gqkv, 256, GEMM_SMEM>>>(xh, wqh, wkh, wvh, q, k, v, DM_, INNER_, 0);
    cudaEventRecord(eQ0, 0);
    hmma_gemm<<<gqkv, 256, GEMM_SMEM>>>(xh, wqh, wkh, wvh, q, k, v, DM_, INNER_, SROWS);
    cudaEventRecord(eQ1, 0);

    // ---- side stream: attention (half-batch chunks) + state ----
    dim3 gattn(HROWS/ATT_S, H_, 1);
    cudaStreamWaitEvent(s1, eQ0, 0);
    attn_kernel<<<gattn, 256, 0, s1>>>(q, k, v, beta, ctab, stab, ah, 0, 0);
    cudaEventRecord(eA0a, s1);
    attn_kernel<<<gattn, 256, 0, s1>>>(q, k, v, beta, ctab, stab, ah, 0, HROWS);
    cudaEventRecord(eA0b, s1);
    state_part<<<H_ * STCH, 256, 0, s1>>>(k, v, beta, alpha_log, ctab, stab, stpart, 0);
    cudaStreamWaitEvent(s1, eQ1, 0);
    attn_kernel<<<gattn, 256, 0, s1>>>(q, k, v, beta, ctab, stab, ah, 1, 0);
    cudaEventRecord(eA1a, s1);
    attn_kernel<<<gattn, 256, 0, s1>>>(q, k, v, beta, ctab, stab, ah, 1, HROWS);
    cudaEventRecord(eA1b, s1);
    state_part<<<H_ * STCH, 256, 0, s1>>>(k, v, beta, alpha_log, ctab, stab, stpart, 1);
    state_comb<<<B_ * H_, 256, 0, s1>>>(stpart, alpha_log, out + (size_t)MROWS * DM_);
    cudaEventRecord(eS, s1);

    // ---- O-proj GEMMs on main stream, half-batch chunks ----
    dim3 gout(DM_/64, HROWS/128, 1);
    cudaStreamWaitEvent(0, eA0a, 0);
    hmma_gemm<<<gout, 256, GEMM_SMEM>>>(ah, woh, woh, woh, out, out, out, INNER_, DM_, 0);
    cudaStreamWaitEvent(0, eA0b, 0);
    hmma_gemm<<<gout, 256, GEMM_SMEM>>>(ah, woh, woh, woh, out, out, out, INNER_, DM_, HROWS);
    cudaStreamWaitEvent(0, eA1a, 0);
    hmma_gemm<<<gout, 256, GEMM_SMEM>>>(ah, woh, woh, woh, out, out, out, INNER_, DM_, SROWS);
    cudaStreamWaitEvent(0, eA1b, 0);
    hmma_gemm<<<gout, 256, GEMM_SMEM>>>(ah, woh, woh, woh, out, out, out, INNER_, DM_, SROWS + HROWS);

    // ---- join side stream back ----
    cudaStreamWaitEvent(0, eS, 0);
}

// round 15
// speedup vs baseline: 1.0387x; 1.0387x over previous
#include <cuda_runtime.h>
#include <cuda_fp16.h>
#include <math.h>
#include <stdint.h>

#define B_ 2
#define S_ 2048
#define DM_ 2048
#define H_ 8
#define DH_ 128
#define INNER_ 1024
#define MROWS (B_*S_)   // 4096
#define SROWS S_        // rows per batch
#define HROWS (S_/2)    // rows per half-batch chunk

// ---------------- scratch (device globals; no allocation allowed) ----------
__device__ float g_q[MROWS * INNER_];
__device__ float g_k[MROWS * INNER_];
__device__ float g_v[MROWS * INNER_];
__device__ float g_beta[MROWS * H_];
__device__ float g_amean[H_];
__device__ float g_ctab[S_ * 64];
__device__ float g_stab[S_ * 64];

__device__ __align__(128) __half g_xh[MROWS * DM_];
__device__ __align__(128) __half g_wqh[INNER_ * DM_];
__device__ __align__(128) __half g_wkh[INNER_ * DM_];
__device__ __align__(128) __half g_wvh[INNER_ * DM_];
__device__ __align__(128) __half g_woh[DM_ * INNER_];
__device__ __align__(128) __half g_ah[MROWS * INNER_];

#define STWIN_ 128
#define STCH 4
#define STLEN (STWIN_/STCH)   // 32
__device__ float g_stpart[B_ * H_ * STCH * DH_ * DH_];

__device__ __forceinline__ float sigmoidf_(float x) {
    return 1.0f / (1.0f + expf(-x));
}

// ======================= PTX helpers ==============================
__device__ __forceinline__ uint32_t smem_u32(const void* p) {
    uint32_t a;
    asm("{ .reg .u64 t; cvta.to.shared.u64 t, %1; cvt.u32.u64 %0, t; }"
        : "=r"(a) : "l"(p));
    return a;
}

#define CP_ASYNC16(dst, src) \
    asm volatile("cp.async.cg.shared.global [%0], [%1], 16;" :: "r"(dst), "l"(src) : "memory")
#define CP_COMMIT() asm volatile("cp.async.commit_group;" ::: "memory")
#define CP_WAIT(n)  asm volatile("cp.async.wait_group %0;" :: "n"(n) : "memory")

__device__ __forceinline__ void ldsm_x4(uint32_t& r0, uint32_t& r1, uint32_t& r2, uint32_t& r3,
                                        uint32_t addr) {
    asm volatile("ldmatrix.sync.aligned.m8n8.x4.shared.b16 {%0,%1,%2,%3}, [%4];"
        : "=r"(r0), "=r"(r1), "=r"(r2), "=r"(r3) : "r"(addr));
}

__device__ __forceinline__ void mma16816(float* c, const uint32_t* a, uint32_t b0, uint32_t b1) {
    asm volatile(
        "mma.sync.aligned.m16n8k16.row.col.f32.f16.f16.f32 "
        "{%0,%1,%2,%3}, {%4,%5,%6,%7}, {%8,%9}, {%0,%1,%2,%3};"
        : "+f"(c[0]), "+f"(c[1]), "+f"(c[2]), "+f"(c[3])
        : "r"(a[0]), "r"(a[1]), "r"(a[2]), "r"(a[3]), "r"(b0), "r"(b1));
}

// ======================= prep_main: x->fp16 + weight->fp16 ==================
__global__ __launch_bounds__(256) void prep_main(
    const float* __restrict__ x,
    const float* __restrict__ Wq, const float* __restrict__ Wk,
    const float* __restrict__ Wv, const float* __restrict__ Wo,
    __half* __restrict__ xh,
    __half* __restrict__ wqh, __half* __restrict__ wkh,
    __half* __restrict__ wvh, __half* __restrict__ woh) {
    int blk = blockIdx.x;
    int tid = threadIdx.x;
    const float* s;
    __half* d;
    int i;
    if (blk < 8192) {
        s = x; d = xh;
        i = blk * 256 + tid;
    } else {
        int idx = blk - 8192;
        int seg = idx >> 11;
        s = (seg == 0) ? Wq : (seg == 1) ? Wk : (seg == 2) ? Wv : Wo;
        d = (seg == 0) ? wqh : (seg == 1) ? wkh : (seg == 2) ? wvh : woh;
        i = (idx & 2047) * 256 + tid;
    }
    float4 v = ((const float4*)s)[i];
    __half2* p = (__half2*)d;
    p[2*i]   = __half2(__float2half(v.x), __float2half(v.y));
    p[2*i+1] = __half2(__float2half(v.z), __float2half(v.w));
}

// ======================= prep_side: beta + rope table + amean ===============
#define PS_BETA MROWS
#define PS_ROPE (PS_BETA + 512)
#define PS_GRID (PS_ROPE + 1)
__global__ __launch_bounds__(256) void prep_side(
    const float* __restrict__ x,
    const float* __restrict__ Wb, const float* __restrict__ bb,
    const float* __restrict__ alpha_log,
    float* __restrict__ beta,
    float* __restrict__ ctab, float* __restrict__ stab) {
    int blk = blockIdx.x;
    int tid = threadIdx.x;
    if (blk < PS_BETA) {
        __shared__ float xs[DM_];
        int row = blk;
        const float4* src = (const float4*)(x + (size_t)row * DM_);
        for (int i = tid; i < DM_/4; i += 256)
            *(float4*)&xs[i*4] = src[i];
        __syncthreads();
        int w = tid >> 5;
        int lane = tid & 31;
        const float* wr = Wb + w * DM_;
        float sum = 0.f;
        for (int i = lane; i < DM_; i += 32)
            sum += xs[i] * wr[i];
        #pragma unroll
        for (int o = 16; o; o >>= 1) sum += __shfl_xor_sync(0xffffffffu, sum, o);
        if (lane == 0) beta[row * H_ + w] = sigmoidf_(sum + bb[w]);
    } else if (blk < PS_ROPE) {
        int idx = (blk - PS_BETA) * 256 + tid;
        int j = idx & 63;
        int s = idx >> 6;
        float ex = (float)(2 * j) * (1.0f / (float)DH_);
        float inv = powf(10000.0f, -ex);
        float sn, c;
        sincosf((float)s * inv, &sn, &c);
        ctab[idx] = c;
        stab[idx] = sn;
    } else {
        int w = tid >> 5;
        int lane = tid & 31;
        float s = 0.f;
        for (int d = lane; d < DH_; d += 32)
            s += sigmoidf_(alpha_log[w * DH_ + d]);
        #pragma unroll
        for (int o = 16; o; o >>= 1) s += __shfl_xor_sync(0xffffffffu, s, o);
        if (lane == 0) g_amean[w] = s / (float)DH_;
    }
}

// ======================= fp16 1-pass HMMA GEMM (r13 config) =================
#define NSTG 3
#define TILE_B 16384u
#define STG_BYTES (2u * TILE_B)       // 32KB
#define GEMM_SMEM (NSTG * STG_BYTES)  // 96KB

__global__ __launch_bounds__(256, 2) void hmma_gemm(
    const __half* __restrict__ Ah,
    const __half* __restrict__ B0, const __half* __restrict__ B1,
    const __half* __restrict__ B2,
    float* __restrict__ C0, float* __restrict__ C1, float* __restrict__ C2,
    int K, int ldc, int m_base) {
    extern __shared__ char smem[];
    uint32_t sm = smem_u32(smem);
    int tid = threadIdx.x;
    int lane = tid & 31;
    int wid = tid >> 5;
    int wm = wid & 1;
    int wn = wid >> 1;
    int m0 = m_base + blockIdx.y * 128;
    int n0 = blockIdx.x * 128;

    const __half* Bh;
    float* C;
    if (blockIdx.z == 0)      { Bh = B0; C = C0; }
    else if (blockIdx.z == 1) { Bh = B1; C = C1; }
    else                      { Bh = B2; C = C2; }

    int kiters = K >> 6;

    float acc[4][4][4];
    #pragma unroll
    for (int i = 0; i < 4; i++)
        #pragma unroll
        for (int j = 0; j < 4; j++)
            #pragma unroll
            for (int t = 0; t < 4; t++) acc[i][j][t] = 0.f;

    int lc = tid & 7;
    int lr = tid >> 3;

    #define ISSUE_STAGE(ip, buf) do {                                          \
        int _k0 = (ip) << 6;                                                   \
        const __half* _ah = Ah + (size_t)(m0 + lr) * K + _k0 + lc * 8;         \
        const __half* _bh = Bh + (size_t)(n0 + lr) * K + _k0 + lc * 8;         \
        uint32_t _sb = sm + (buf) * STG_BYTES;                                 \
        _Pragma("unroll")                                                      \
        for (int _i = 0; _i < 4; _i++) {                                       \
            int _row = lr + 32 * _i;                                           \
            uint32_t _sw = ((uint32_t)_row << 7) + (((uint32_t)(lc ^ (_row & 7))) << 4); \
            size_t _go = (size_t)(32 * _i) * K;                                \
            CP_ASYNC16(_sb + _sw,          _ah + _go);                         \
            CP_ASYNC16(_sb + TILE_B + _sw, _bh + _go);                         \
        }                                                                      \
    } while (0)

    ISSUE_STAGE(0, 0); CP_COMMIT();
    ISSUE_STAGE(1, 1); CP_COMMIT();

    for (int it = 0; it < kiters; ++it) {
        if (it + 1 < kiters) { CP_WAIT(1); } else { CP_WAIT(0); }
        __syncthreads();
        if (it + 2 < kiters) {
            int nb = it + 2; while (nb >= 3) nb -= 3;
            ISSUE_STAGE(it + 2, nb);
            CP_COMMIT();
        }
        int cb = it; while (cb >= 3) cb -= 3;
        uint32_t sah = sm + cb * STG_BYTES;
        uint32_t sbh = sah + TILE_B;
        #pragma unroll
        for (int ks = 0; ks < 4; ++ks) {
            int ch = ks * 2 + (lane >> 4);
            uint32_t bfr[2][4];
            #pragma unroll
            for (int nt2 = 0; nt2 < 2; ++nt2) {
                int rowB = wn * 32 + nt2 * 16 + (lane & 7) + ((lane >> 3) & 1) * 8;
                uint32_t off = ((uint32_t)rowB << 7) + (((uint32_t)(ch ^ (rowB & 7))) << 4);
                ldsm_x4(bfr[nt2][0], bfr[nt2][1], bfr[nt2][2], bfr[nt2][3], sbh + off);
            }
            #pragma unroll
            for (int mt = 0; mt < 4; ++mt) {
                int rowA = wm * 64 + mt * 16 + (lane & 7) + ((lane >> 3) & 1) * 8;
                uint32_t off = ((uint32_t)rowA << 7) + (((uint32_t)(ch ^ (rowA & 7))) << 4);
                uint32_t a[4];
                ldsm_x4(a[0], a[1], a[2], a[3], sah + off);
                #pragma unroll
                for (int nt2 = 0; nt2 < 2; ++nt2) {
                    mma16816(acc[mt][nt2 * 2 + 0], a, bfr[nt2][0], bfr[nt2][2]);
                    mma16816(acc[mt][nt2 * 2 + 1], a, bfr[nt2][1], bfr[nt2][3]);
                }
            }
        }
    }
    #undef ISSUE_STAGE

    #pragma unroll
    for (int mt = 0; mt < 4; ++mt) {
        int m = m0 + wm * 64 + mt * 16 + (lane >> 2);
        #pragma unroll
        for (int nt = 0; nt < 4; ++nt) {
            int n = n0 + wn * 32 + nt * 8 + (lane & 3) * 2;
            float* p = C + (size_t)m * ldc + n;
            *(float2*)p = make_float2(acc[mt][nt][0], acc[mt][nt][1]);
            *(float2*)(p + 8 * (size_t)ldc) = make_float2(acc[mt][nt][2], acc[mt][nt][3]);
        }
    }
}

// ---------------- attention: 2 q-rows per warp, shared k/v reads -----------
#define WIN_ 32
#define ATT_S 16
#define ATT_ROWS (WIN_ - 1 + ATT_S)   // 47
__global__ __launch_bounds__(256) void attn_kernel(const float* __restrict__ q,
                                                   const float* __restrict__ k,
                                                   const float* __restrict__ v,
                                                   const float* __restrict__ beta,
                                                   const float* __restrict__ ctab,
                                                   const float* __restrict__ stab,
                                                   __half* __restrict__ ah,
                                                   int b, int s_base) {
    __shared__ float ks[ATT_ROWS * DH_];
    __shared__ float vs[ATT_ROWS * DH_];
    __shared__ float bs[ATT_ROWS];
    int tid = threadIdx.x;
    int wid = tid >> 5;
    int lane = tid & 31;
    int s0 = s_base + blockIdx.x * ATT_S;
    int h  = blockIdx.y;
    int base_t = s0 - (WIN_ - 1);

    size_t bh = (size_t)b * S_ * INNER_ + h * DH_;

    // stage raw k/v + beta (zero-fill t<0)
    for (int i = tid; i < ATT_ROWS * 32; i += 256) {
        int r = i >> 5;
        int c = (i & 31) * 4;
        int t = base_t + r;
        float4 z = make_float4(0.f, 0.f, 0.f, 0.f);
        float4 kv = z, vv = z;
        if (t >= 0) {
            kv = *(const float4*)(k + bh + (size_t)t * INNER_ + c);
            vv = *(const float4*)(v + bh + (size_t)t * INNER_ + c);
        }
        *(float4*)&ks[r * DH_ + c] = kv;
        *(float4*)&vs[r * DH_ + c] = vv;
    }
    if (tid < ATT_ROWS) {
        int t = base_t + tid;
        bs[tid] = (t >= 0) ? beta[(size_t)(b * S_ + t) * H_ + h] : 0.f;
    }
    __syncthreads();

    // rope k in place
    for (int i = tid; i < ATT_ROWS * 16; i += 256) {
        int r = i >> 4;
        int c = (i & 15) * 4;
        int t = base_t + r;
        if (t < 0) continue;
        float4 a = *(float4*)&ks[r * DH_ + c];
        float4 p = *(float4*)&ks[r * DH_ + c + 64];
        float4 ct4 = *(const float4*)&ctab[(size_t)t * 64 + c];
        float4 st4 = *(const float4*)&stab[(size_t)t * 64 + c];
        float4 lo, hi;
        lo.x = a.x*ct4.x - p.x*st4.x;  hi.x = p.x*ct4.x + a.x*st4.x;
        lo.y = a.y*ct4.y - p.y*st4.y;  hi.y = p.y*ct4.y + a.y*st4.y;
        lo.z = a.z*ct4.z - p.z*st4.z;  hi.z = p.z*ct4.z + a.z*st4.z;
        lo.w = a.w*ct4.w - p.w*st4.w;  hi.w = p.w*ct4.w + a.w*st4.w;
        *(float4*)&ks[r * DH_ + c]      = lo;
        *(float4*)&ks[r * DH_ + c + 64] = hi;
    }
    __syncthreads();

    int sA = s0 + 2 * wid;
    int sB = sA + 1;
    float am = g_amean[h];
    float am2 = am * am;
    float am3 = am2 * am;
    float am4 = am2 * am2;
    int c4 = lane * 4;
    int jj = (lane & 15) * 4;

    // load + rope qA and qB (partner lane = lane^16)
    float4 qA, qB;
    {
        float4 qraw = *(const float4*)(q + bh + (size_t)sA * INNER_ + c4);
        float4 ct4 = *(const float4*)&ctab[(size_t)sA * 64 + jj];
        float4 st4 = *(const float4*)&stab[(size_t)sA * 64 + jj];
        float px = __shfl_xor_sync(0xffffffffu, qraw.x, 16);
        float py = __shfl_xor_sync(0xffffffffu, qraw.y, 16);
        float pz = __shfl_xor_sync(0xffffffffu, qraw.z, 16);
        float pw = __shfl_xor_sync(0xffffffffu, qraw.w, 16);
        if (lane < 16) {
            qA.x = qraw.x*ct4.x - px*st4.x;
            qA.y = qraw.y*ct4.y - py*st4.y;
            qA.z = qraw.z*ct4.z - pz*st4.z;
            qA.w = qraw.w*ct4.w - pw*st4.w;
        } else {
            qA.x = qraw.x*ct4.x + px*st4.x;
            qA.y = qraw.y*ct4.y + py*st4.y;
            qA.z = qraw.z*ct4.z + pz*st4.z;
            qA.w = qraw.w*ct4.w + pw*st4.w;
        }
    }
    {
        float4 qraw = *(const float4*)(q + bh + (size_t)sB * INNER_ + c4);
        float4 ct4 = *(const float4*)&ctab[(size_t)sB * 64 + jj];
        float4 st4 = *(const float4*)&stab[(size_t)sB * 64 + jj];
        float px = __shfl_xor_sync(0xffffffffu, qraw.x, 16);
        float py = __shfl_xor_sync(0xffffffffu, qraw.y, 16);
        float pz = __shfl_xor_sync(0xffffffffu, qraw.z, 16);
        float pw = __shfl_xor_sync(0xffffffffu, qraw.w, 16);
        if (lane < 16) {
            qB.x = qraw.x*ct4.x - px*st4.x;
            qB.y = qraw.y*ct4.y - py*st4.y;
            qB.z = qraw.z*ct4.z - pz*st4.z;
            qB.w = qraw.w*ct4.w - pw*st4.w;
        } else {
            qB.x = qraw.x*ct4.x + px*st4.x;
            qB.y = qraw.y*ct4.y + py*st4.y;
            qB.z = qraw.z*ct4.z + pz*st4.z;
            qB.w = qraw.w*ct4.w + pw*st4.w;
        }
    }

    float4 accA = make_float4(0.f, 0.f, 0.f, 0.f);
    float4 accB = make_float4(0.f, 0.f, 0.f, 0.f);
    int rB = sB - base_t;   // = 2*wid + 32

    // j = 0: only sB sees t = sB
    {
        float4 k0 = *(const float4*)&ks[rB * DH_ + c4];
        float4 v0 = *(const float4*)&vs[rB * DH_ + c4];
        float d = qB.x*k0.x + qB.y*k0.y + qB.z*k0.z + qB.w*k0.w;
        #pragma unroll
        for (int o = 16; o; o >>= 1) d += __shfl_xor_sync(0xffffffffu, d, o);
        float w = d * bs[rB];
        accB.x = fmaf(w, v0.x, accB.x);
        accB.y = fmaf(w, v0.y, accB.y);
        accB.z = fmaf(w, v0.z, accB.z);
        accB.w = fmaf(w, v0.w, accB.w);
    }

    // groups: j = 1+4g .. 4+4g, g = 0..7  (j in [1,32])
    float decayA = 1.f;   // am^(j-1) at group start
    #pragma unroll
    for (int g = 0; g < 8; ++g) {
        int r0 = rB - 1 - 4 * g;
        float4 k0 = *(const float4*)&ks[(r0  ) * DH_ + c4];
        float4 v0 = *(const float4*)&vs[(r0  ) * DH_ + c4];
        float4 k1 = *(const float4*)&ks[(r0-1) * DH_ + c4];
        float4 v1 = *(const float4*)&vs[(r0-1) * DH_ + c4];
        float4 k2 = *(const float4*)&ks[(r0-2) * DH_ + c4];
        float4 v2 = *(const float4*)&vs[(r0-2) * DH_ + c4];
        float4 k3 = *(const float4*)&ks[(r0-3) * DH_ + c4];
        float4 v3 = *(const float4*)&vs[(r0-3) * DH_ + c4];
        float dA0 = qA.x*k0.x + qA.y*k0.y + qA.z*k0.z + qA.w*k0.w;
        float dB0 = qB.x*k0.x + qB.y*k0.y + qB.z*k0.z + qB.w*k0.w;
        float dA1 = qA.x*k1.x + qA.y*k1.y + qA.z*k1.z + qA.w*k1.w;
        float dB1 = qB.x*k1.x + qB.y*k1.y + qB.z*k1.z + qB.w*k1.w;
        float dA2 = qA.x*k2.x + qA.y*k2.y + qA.z*k2.z + qA.w*k2.w;
        float dB2 = qB.x*k2.x + qB.y*k2.y + qB.z*k2.z + qB.w*k2.w;
        float dA3 = qA.x*k3.x + qA.y*k3.y + qA.z*k3.z + qA.w*k3.w;
        float dB3 = qB.x*k3.x + qB.y*k3.y + qB.z*k3.z + qB.w*k3.w;
        #pragma unroll
        for (int o = 16; o; o >>= 1) {
            dA0 += __shfl_xor_sync(0xffffffffu, dA0, o);
            dB0 += __shfl_xor_sync(0xffffffffu, dB0, o);
            dA1 += __shfl_xor_sync(0xffffffffu, dA1, o);
            dB1 += __shfl_xor_sync(0xffffffffu, dB1, o);
            dA2 += __shfl_xor_sync(0xffffffffu, dA2, o);
            dB2 += __shfl_xor_sync(0xffffffffu, dB2, o);
            dA3 += __shfl_xor_sync(0xffffffffu, dA3, o);
            dB3 += __shfl_xor_sync(0xffffffffu, dB3, o);
        }
        float b0 = bs[r0], b1 = bs[r0-1], b2 = bs[r0-2], b3 = bs[r0-3];
        float wA0 = dA0 * decayA * b0;
        float wA1 = dA1 * decayA * am  * b1;
        float wA2 = dA2 * decayA * am2 * b2;
        float wA3 = dA3 * decayA * am3 * b3;
        float wB0 = dB0 * decayA * am  * b0;
        float wB1 = dB1 * decayA * am2 * b1;
        float wB2 = dB2 * decayA * am3 * b2;
        float wB3 = (g < 7) ? dB3 * decayA * am4 * b3 : 0.f;   // j=32 invalid for sB
        accA.x = fmaf(wA0, v0.x, fmaf(wA1, v1.x, fmaf(wA2, v2.x, fmaf(wA3, v3.x, accA.x))));
        accA.y = fmaf(wA0, v0.y, fmaf(wA1, v1.y, fmaf(wA2, v2.y, fmaf(wA3, v3.y, accA.y))));
        accA.z = fmaf(wA0, v0.z, fmaf(wA1, v1.z, fmaf(wA2, v2.z, fmaf(wA3, v3.z, accA.z))));
        accA.w = fmaf(wA0, v0.w, fmaf(wA1, v1.w, fmaf(wA2, v2.w, fmaf(wA3, v3.w, accA.w))));
        accB.x = fmaf(wB0, v0.x, fmaf(wB1, v1.x, fmaf(wB2, v2.x, fmaf(wB3, v3.x, accB.x))));
        accB.y = fmaf(wB0, v0.y, fmaf(wB1, v1.y, fmaf(wB2, v2.y, fmaf(wB3, v3.y, accB.y))));
        accB.z = fmaf(wB0, v0.z, fmaf(wB1, v1.z, fmaf(wB2, v2.z, fmaf(wB3, v3.z, accB.z))));
        accB.w = fmaf(wB0, v0.w, fmaf(wB1, v1.w, fmaf(wB2, v2.w, fmaf(wB3, v3.w, accB.w))));
        decayA *= am4;
    }

    size_t oA = bh + (size_t)sA * INNER_ + c4;
    size_t oB = bh + (size_t)sB * INNER_ + c4;
    ((__half2*)(ah + oA))[0] = __half2(__float2half(accA.x), __float2half(accA.y));
    ((__half2*)(ah + oA))[1] = __half2(__float2half(accA.z), __float2half(accA.w));
    ((__half2*)(ah + oB))[0] = __half2(__float2half(accB.x), __float2half(accB.y));
    ((__half2*)(ah + oB))[1] = __half2(__float2half(accB.z), __float2half(accB.w));
}

// ---------------- recurrent state: partial chunks + combine ----------------
__global__ __launch_bounds__(256) void state_part(const float* __restrict__ k,
                                                  const float* __restrict__ v,
                                                  const float* __restrict__ beta,
                                                  const float* __restrict__ alpha_log,
                                                  const float* __restrict__ ctab,
                                                  const float* __restrict__ stab,
                                                  float* __restrict__ part,
                                                  int b) {
    int h  = blockIdx.x >> 2;
    int c  = blockIdx.x & 3;
    int bh = b * H_ + h;
    int tid = threadIdx.x;
    int d = tid >> 1;
    int e0 = (tid & 1) * 64;
    __shared__ float ks[DH_], vs[DH_];
    float st[64];
    #pragma unroll
    for (int e = 0; e < 64; e++) st[e] = 0.f;
    float ad = sigmoidf_(alpha_log[h * DH_ + d]);
    int tbeg = S_ - STWIN_ + c * STLEN;
    for (int t = tbeg; t < tbeg + STLEN; t++) {
        __syncthreads();
        size_t base = (size_t)(b * S_ + t) * INNER_ + h * DH_;
        if (tid < 128) ks[tid] = k[base + tid];
        else           vs[tid - 128] = v[base + tid - 128];
        __syncthreads();
        float cv = ctab[(size_t)t * 64 + (d & 63)];
        float sv = stab[(size_t)t * 64 + (d & 63)];
        float kd = (d < 64) ? ks[d] * cv - ks[d + 64] * sv
                            : ks[d] * cv + ks[d - 64] * sv;
        float kb = kd * beta[(b * S_ + t) * H_ + h];
        #pragma unroll
        for (int e = 0; e < 64; e++)
            st[e] = fmaf(ad, st[e], kb * vs[e0 + e]);
    }
    float* op = part + (((size_t)bh * STCH + c) * DH_ + d) * DH_ + e0;
    #pragma unroll
    for (int e = 0; e < 64; e++) op[e] = st[e];
}

__global__ __launch_bounds__(256) void state_comb(const float* __restrict__ part,
                                                  const float* __restrict__ alpha_log,
                                                  float* __restrict__ stout) {
    int bh = blockIdx.x;
    int h = bh & 7;
    int tid = threadIdx.x;
    int d = tid >> 1;
    int e0 = (tid & 1) * 64;
    float ad = sigmoidf_(alpha_log[h * DH_ + d]);
    float a32 = ad;
    a32 *= a32; a32 *= a32; a32 *= a32; a32 *= a32; a32 *= a32;
    const float* p0 = part + (((size_t)bh * STCH + 0) * DH_ + d) * DH_ + e0;
    const float* p1 = part + (((size_t)bh * STCH + 1) * DH_ + d) * DH_ + e0;
    const float* p2 = part + (((size_t)bh * STCH + 2) * DH_ + d) * DH_ + e0;
    const float* p3 = part + (((size_t)bh * STCH + 3) * DH_ + d) * DH_ + e0;
    float* op = stout + ((size_t)bh * DH_ + d) * DH_ + e0;
    #pragma unroll
    for (int e = 0; e < 64; e++) {
        float r = p0[e];
        r = fmaf(r, a32, p1[e]);
        r = fmaf(r, a32, p2[e]);
        r = fmaf(r, a32, p3[e]);
        op[e] = r;
    }
}

// ---------------- launch ----------------
extern "C" void kernel_launch(void* const* d_in, const int* in_sizes, int n_in,
                              void* d_out, int out_size) {
    const float* x         = (const float*)d_in[0];
    const float* Wq        = (const float*)d_in[1];
    const float* Wk        = (const float*)d_in[2];
    const float* Wv        = (const float*)d_in[3];
    const float* Wo        = (const float*)d_in[4];
    const float* Wb        = (const float*)d_in[5];
    const float* bb        = (const float*)d_in[6];
    const float* alpha_log = (const float*)d_in[7];
    float* out = (float*)d_out;

    float *q, *k, *v, *beta, *stpart, *ctab, *stab;
    cudaGetSymbolAddress((void**)&q,      g_q);
    cudaGetSymbolAddress((void**)&k,      g_k);
    cudaGetSymbolAddress((void**)&v,      g_v);
    cudaGetSymbolAddress((void**)&beta,   g_beta);
    cudaGetSymbolAddress((void**)&stpart, g_stpart);
    cudaGetSymbolAddress((void**)&ctab,   g_ctab);
    cudaGetSymbolAddress((void**)&stab,   g_stab);
    __half *xh, *wqh, *wkh, *wvh, *woh, *ah;
    cudaGetSymbolAddress((void**)&xh,  g_xh);
    cudaGetSymbolAddress((void**)&wqh, g_wqh);
    cudaGetSymbolAddress((void**)&wkh, g_wkh);
    cudaGetSymbolAddress((void**)&wvh, g_wvh);
    cudaGetSymbolAddress((void**)&woh, g_woh);
    cudaGetSymbolAddress((void**)&ah,  g_ah);

    // one-time resources (host-side handles, no device memory)
    static cudaStream_t s1 = 0;
    static cudaEvent_t eQ0, eQ1, eA0a, eA0b, eA1a, eA1b, eS;
    if (!s1) {
        cudaStreamCreateWithFlags(&s1, cudaStreamNonBlocking);
        cudaEventCreateWithFlags(&eQ0,  cudaEventDisableTiming);
        cudaEventCreateWithFlags(&eQ1,  cudaEventDisableTiming);
        cudaEventCreateWithFlags(&eA0a, cudaEventDisableTiming);
        cudaEventCreateWithFlags(&eA0b, cudaEventDisableTiming);
        cudaEventCreateWithFlags(&eA1a, cudaEventDisableTiming);
        cudaEventCreateWithFlags(&eA1b, cudaEventDisableTiming);
        cudaEventCreateWithFlags(&eS,   cudaEventDisableTiming);
        cudaFuncSetAttribute(hmma_gemm, cudaFuncAttributeMaxDynamicSharedMemorySize, GEMM_SMEM);
    }

    // ---- prep: main-stream (xh + weights) ∥ side-stream (beta/rope/amean) --
    prep_main<<<16384, 256>>>(x, Wq, Wk, Wv, Wo, xh, wqh, wkh, wvh, woh);
    prep_side<<<PS_GRID, 256, 0, s1>>>(x, Wb, bb, alpha_log, beta, ctab, stab);

    // ---- QKV GEMMs, split by batch ----
    dim3 gqkv(INNER_/128, SROWS/128, 3);
    hmma_gemm<<<gqkv, 256, GEMM_SMEM>>>(xh, wqh, wkh, wvh, q, k, v, DM_, INNER_, 0);
    cudaEventRecord(eQ0, 0);
    hmma_gemm<<<gqkv, 256, GEMM_SMEM>>>(xh, wqh, wkh, wvh, q, k, v, DM_, INNER_, SROWS);
    cudaEventRecord(eQ1, 0);

    // ---- side stream: attention (half-batch chunks) + state ----
    dim3 gattn(HROWS/ATT_S, H_, 1);
    cudaStreamWaitEvent(s1, eQ0, 0);
    attn_kernel<<<gattn, 256, 0, s1>>>(q, k, v, beta, ctab, stab, ah, 0, 0);
    cudaEventRecord(eA0a, s1);
    attn_kernel<<<gattn, 256, 0, s1>>>(q, k, v, beta, ctab, stab, ah, 0, HROWS);
    cudaEventRecord(eA0b, s1);
    state_part<<<H_ * STCH, 256, 0, s1>>>(k, v, beta, alpha_log, ctab, stab, stpart, 0);
    cudaStreamWaitEvent(s1, eQ1, 0);
    attn_kernel<<<gattn, 256, 0, s1>>>(q, k, v, beta, ctab, stab, ah, 1, 0);
    cudaEventRecord(eA1a, s1);
    attn_kernel<<<gattn, 256, 0, s1>>>(q, k, v, beta, ctab, stab, ah, 1, HROWS);
    cudaEventRecord(eA1b, s1);
    state_part<<<H_ * STCH, 256, 0, s1>>>(k, v, beta, alpha_log, ctab, stab, stpart, 1);
    state_comb<<<B_ * H_, 256, 0, s1>>>(stpart, alpha_log, out + (size_t)MROWS * DM_);
    cudaEventRecord(eS, s1);

    // ---- O-proj GEMMs on main stream, half-batch chunks ----
    dim3 gout(DM_/128, HROWS/128, 1);
    cudaStreamWaitEvent(0, eA0a, 0);
    hmma_gemm<<<gout, 256, GEMM_SMEM>>>(ah, woh, woh, woh, out, out, out, INNER_, DM_, 0);
    cudaStreamWaitEvent(0, eA0b, 0);
    hmma_gemm<<<gout, 256, GEMM_SMEM>>>(ah, woh, woh, woh, out, out, out, INNER_, DM_, HROWS);
    cudaStreamWaitEvent(0, eA1a, 0);
    hmma_gemm<<<gout, 256, GEMM_SMEM>>>(ah, woh, woh, woh, out, out, out, INNER_, DM_, SROWS);
    cudaStreamWaitEvent(0, eA1b, 0);
    hmma_gemm<<<gout, 256, GEMM_SMEM>>>(ah, woh, woh, woh, out, out, out, INNER_, DM_, SROWS + HROWS);

    // ---- join side stream back ----
    cudaStreamWaitEvent(0, eS, 0);
}

// round 16
// speedup vs baseline: 1.1231x; 1.0812x over previous
#include <cuda_runtime.h>
#include <cuda_fp16.h>
#include <math.h>
#include <stdint.h>

#define B_ 2
#define S_ 2048
#define DM_ 2048
#define H_ 8
#define DH_ 128
#define INNER_ 1024
#define MROWS (B_*S_)   // 4096
#define SROWS S_        // rows per batch
#define HROWS (S_/2)    // rows per half-batch chunk

// ---------------- scratch (device globals; no allocation allowed) ----------
__device__ float g_q[MROWS * INNER_];
__device__ float g_k[MROWS * INNER_];
__device__ float g_v[MROWS * INNER_];
__device__ float g_beta[MROWS * H_];
__device__ float g_amean[H_];
__device__ float g_ctab[S_ * 64];
__device__ float g_stab[S_ * 64];

__device__ __align__(128) __half g_xh[MROWS * DM_];
__device__ __align__(128) __half g_wqh[INNER_ * DM_];
__device__ __align__(128) __half g_wkh[INNER_ * DM_];
__device__ __align__(128) __half g_wvh[INNER_ * DM_];
__device__ __align__(128) __half g_woh[DM_ * INNER_];
__device__ __align__(128) __half g_ah[MROWS * INNER_];

#define STWIN_ 128
#define STCH 4
#define STLEN (STWIN_/STCH)   // 32
__device__ float g_stpart[B_ * H_ * STCH * DH_ * DH_];

__device__ __forceinline__ float sigmoidf_(float x) {
    return 1.0f / (1.0f + expf(-x));
}

// ======================= PTX helpers ==============================
__device__ __forceinline__ uint32_t smem_u32(const void* p) {
    uint32_t a;
    asm("{ .reg .u64 t; cvta.to.shared.u64 t, %1; cvt.u32.u64 %0, t; }"
        : "=r"(a) : "l"(p));
    return a;
}

#define CP_ASYNC16(dst, src) \
    asm volatile("cp.async.cg.shared.global [%0], [%1], 16;" :: "r"(dst), "l"(src) : "memory")
#define CP_COMMIT() asm volatile("cp.async.commit_group;" ::: "memory")
#define CP_WAIT(n)  asm volatile("cp.async.wait_group %0;" :: "n"(n) : "memory")

__device__ __forceinline__ void ldsm_x4(uint32_t& r0, uint32_t& r1, uint32_t& r2, uint32_t& r3,
                                        uint32_t addr) {
    asm volatile("ldmatrix.sync.aligned.m8n8.x4.shared.b16 {%0,%1,%2,%3}, [%4];"
        : "=r"(r0), "=r"(r1), "=r"(r2), "=r"(r3) : "r"(addr));
}

__device__ __forceinline__ void mma16816(float* c, const uint32_t* a, uint32_t b0, uint32_t b1) {
    asm volatile(
        "mma.sync.aligned.m16n8k16.row.col.f32.f16.f16.f32 "
        "{%0,%1,%2,%3}, {%4,%5,%6,%7}, {%8,%9}, {%0,%1,%2,%3};"
        : "+f"(c[0]), "+f"(c[1]), "+f"(c[2]), "+f"(c[3])
        : "r"(a[0]), "r"(a[1]), "r"(a[2]), "r"(a[3]), "r"(b0), "r"(b1));
}

// ======================= prep_main: x->fp16 + weight->fp16 ==================
__global__ __launch_bounds__(256) void prep_main(
    const float* __restrict__ x,
    const float* __restrict__ Wq, const float* __restrict__ Wk,
    const float* __restrict__ Wv, const float* __restrict__ Wo,
    __half* __restrict__ xh,
    __half* __restrict__ wqh, __half* __restrict__ wkh,
    __half* __restrict__ wvh, __half* __restrict__ woh) {
    int blk = blockIdx.x;
    int tid = threadIdx.x;
    const float* s;
    __half* d;
    int i;
    if (blk < 8192) {
        s = x; d = xh;
        i = blk * 256 + tid;
    } else {
        int idx = blk - 8192;
        int seg = idx >> 11;
        s = (seg == 0) ? Wq : (seg == 1) ? Wk : (seg == 2) ? Wv : Wo;
        d = (seg == 0) ? wqh : (seg == 1) ? wkh : (seg == 2) ? wvh : woh;
        i = (idx & 2047) * 256 + tid;
    }
    float4 v = ((const float4*)s)[i];
    __half2* p = (__half2*)d;
    p[2*i]   = __half2(__float2half(v.x), __float2half(v.y));
    p[2*i+1] = __half2(__float2half(v.z), __float2half(v.w));
}

// ======================= prep_side: beta + rope table + amean ===============
#define PS_BETA MROWS
#define PS_ROPE (PS_BETA + 512)
#define PS_GRID (PS_ROPE + 1)
__global__ __launch_bounds__(256) void prep_side(
    const float* __restrict__ x,
    const float* __restrict__ Wb, const float* __restrict__ bb,
    const float* __restrict__ alpha_log,
    float* __restrict__ beta,
    float* __restrict__ ctab, float* __restrict__ stab) {
    int blk = blockIdx.x;
    int tid = threadIdx.x;
    if (blk < PS_BETA) {
        __shared__ float xs[DM_];
        int row = blk;
        const float4* src = (const float4*)(x + (size_t)row * DM_);
        for (int i = tid; i < DM_/4; i += 256)
            *(float4*)&xs[i*4] = src[i];
        __syncthreads();
        int w = tid >> 5;
        int lane = tid & 31;
        const float* wr = Wb + w * DM_;
        float sum = 0.f;
        for (int i = lane; i < DM_; i += 32)
            sum += xs[i] * wr[i];
        #pragma unroll
        for (int o = 16; o; o >>= 1) sum += __shfl_xor_sync(0xffffffffu, sum, o);
        if (lane == 0) beta[row * H_ + w] = sigmoidf_(sum + bb[w]);
    } else if (blk < PS_ROPE) {
        int idx = (blk - PS_BETA) * 256 + tid;
        int j = idx & 63;
        int s = idx >> 6;
        float ex = (float)(2 * j) * (1.0f / (float)DH_);
        float inv = powf(10000.0f, -ex);
        float sn, c;
        sincosf((float)s * inv, &sn, &c);
        ctab[idx] = c;
        stab[idx] = sn;
    } else {
        int w = tid >> 5;
        int lane = tid & 31;
        float s = 0.f;
        for (int d = lane; d < DH_; d += 32)
            s += sigmoidf_(alpha_log[w * DH_ + d]);
        #pragma unroll
        for (int o = 16; o; o >>= 1) s += __shfl_xor_sync(0xffffffffu, s, o);
        if (lane == 0) g_amean[w] = s / (float)DH_;
    }
}

// ======================= fp16 1-pass HMMA GEMM ==============================
#define NSTG 3
#define TILE_B 16384u
#define STG_BYTES (2u * TILE_B)       // 32KB
#define GEMM_SMEM (NSTG * STG_BYTES)  // 96KB

__global__ __launch_bounds__(256, 2) void hmma_gemm(
    const __half* __restrict__ Ah,
    const __half* __restrict__ B0, const __half* __restrict__ B1,
    const __half* __restrict__ B2,
    float* __restrict__ C0, float* __restrict__ C1, float* __restrict__ C2,
    int K, int ldc, int m_base) {
    extern __shared__ char smem[];
    uint32_t sm = smem_u32(smem);
    int tid = threadIdx.x;
    int lane = tid & 31;
    int wid = tid >> 5;
    int wm = wid & 1;
    int wn = wid >> 1;
    int m0 = m_base + blockIdx.y * 128;
    int n0 = blockIdx.x * 128;

    const __half* Bh;
    float* C;
    if (blockIdx.z == 0)      { Bh = B0; C = C0; }
    else if (blockIdx.z == 1) { Bh = B1; C = C1; }
    else                      { Bh = B2; C = C2; }

    int kiters = K >> 6;

    float acc[4][4][4];
    #pragma unroll
    for (int i = 0; i < 4; i++)
        #pragma unroll
        for (int j = 0; j < 4; j++)
            #pragma unroll
            for (int t = 0; t < 4; t++) acc[i][j][t] = 0.f;

    int lc = tid & 7;
    int lr = tid >> 3;

    #define ISSUE_STAGE(ip, buf) do {                                          \
        int _k0 = (ip) << 6;                                                   \
        const __half* _ah = Ah + (size_t)(m0 + lr) * K + _k0 + lc * 8;         \
        const __half* _bh = Bh + (size_t)(n0 + lr) * K + _k0 + lc * 8;         \
        uint32_t _sb = sm + (buf) * STG_BYTES;                                 \
        _Pragma("unroll")                                                      \
        for (int _i = 0; _i < 4; _i++) {                                       \
            int _row = lr + 32 * _i;                                           \
            uint32_t _sw = ((uint32_t)_row << 7) + (((uint32_t)(lc ^ (_row & 7))) << 4); \
            size_t _go = (size_t)(32 * _i) * K;                                \
            CP_ASYNC16(_sb + _sw,          _ah + _go);                         \
            CP_ASYNC16(_sb + TILE_B + _sw, _bh + _go);                         \
        }                                                                      \
    } while (0)

    ISSUE_STAGE(0, 0); CP_COMMIT();
    ISSUE_STAGE(1, 1); CP_COMMIT();

    for (int it = 0; it < kiters; ++it) {
        if (it + 1 < kiters) { CP_WAIT(1); } else { CP_WAIT(0); }
        __syncthreads();
        if (it + 2 < kiters) {
            int nb = it + 2; while (nb >= 3) nb -= 3;
            ISSUE_STAGE(it + 2, nb);
            CP_COMMIT();
        }
        int cb = it; while (cb >= 3) cb -= 3;
        uint32_t sah = sm + cb * STG_BYTES;
        uint32_t sbh = sah + TILE_B;
        #pragma unroll
        for (int ks = 0; ks < 4; ++ks) {
            int ch = ks * 2 + (lane >> 4);
            uint32_t bfr[2][4];
            #pragma unroll
            for (int nt2 = 0; nt2 < 2; ++nt2) {
                int rowB = wn * 32 + nt2 * 16 + (lane & 7) + ((lane >> 3) & 1) * 8;
                uint32_t off = ((uint32_t)rowB << 7) + (((uint32_t)(ch ^ (rowB & 7))) << 4);
                ldsm_x4(bfr[nt2][0], bfr[nt2][1], bfr[nt2][2], bfr[nt2][3], sbh + off);
            }
            #pragma unroll
            for (int mt = 0; mt < 4; ++mt) {
                int rowA = wm * 64 + mt * 16 + (lane & 7) + ((lane >> 3) & 1) * 8;
                uint32_t off = ((uint32_t)rowA << 7) + (((uint32_t)(ch ^ (rowA & 7))) << 4);
                uint32_t a[4];
                ldsm_x4(a[0], a[1], a[2], a[3], sah + off);
                #pragma unroll
                for (int nt2 = 0; nt2 < 2; ++nt2) {
                    mma16816(acc[mt][nt2 * 2 + 0], a, bfr[nt2][0], bfr[nt2][2]);
                    mma16816(acc[mt][nt2 * 2 + 1], a, bfr[nt2][1], bfr[nt2][3]);
                }
            }
        }
    }
    #undef ISSUE_STAGE

    #pragma unroll
    for (int mt = 0; mt < 4; ++mt) {
        int m = m0 + wm * 64 + mt * 16 + (lane >> 2);
        #pragma unroll
        for (int nt = 0; nt < 4; ++nt) {
            int n = n0 + wn * 32 + nt * 8 + (lane & 3) * 2;
            float* p = C + (size_t)m * ldc + n;
            *(float2*)p = make_float2(acc[mt][nt][0], acc[mt][nt][1]);
            *(float2*)(p + 8 * (size_t)ldc) = make_float2(acc[mt][nt][2], acc[mt][nt][3]);
        }
    }
}

// ---------------- attention: 2 q-rows per warp, shared k/v reads -----------
#define WIN_ 32
#define ATT_S 16
#define ATT_ROWS (WIN_ - 1 + ATT_S)   // 47
__global__ __launch_bounds__(256) void attn_kernel(const float* __restrict__ q,
                                                   const float* __restrict__ k,
                                                   const float* __restrict__ v,
                                                   const float* __restrict__ beta,
                                                   const float* __restrict__ ctab,
                                                   const float* __restrict__ stab,
                                                   __half* __restrict__ ah,
                                                   int b, int s_base) {
    __shared__ float ks[ATT_ROWS * DH_];
    __shared__ float vs[ATT_ROWS * DH_];
    __shared__ float bs[ATT_ROWS];
    int tid = threadIdx.x;
    int wid = tid >> 5;
    int lane = tid & 31;
    int s0 = s_base + blockIdx.x * ATT_S;
    int h  = blockIdx.y;
    int base_t = s0 - (WIN_ - 1);

    size_t bh = (size_t)b * S_ * INNER_ + h * DH_;

    for (int i = tid; i < ATT_ROWS * 32; i += 256) {
        int r = i >> 5;
        int c = (i & 31) * 4;
        int t = base_t + r;
        float4 z = make_float4(0.f, 0.f, 0.f, 0.f);
        float4 kv = z, vv = z;
        if (t >= 0) {
            kv = *(const float4*)(k + bh + (size_t)t * INNER_ + c);
            vv = *(const float4*)(v + bh + (size_t)t * INNER_ + c);
        }
        *(float4*)&ks[r * DH_ + c] = kv;
        *(float4*)&vs[r * DH_ + c] = vv;
    }
    if (tid < ATT_ROWS) {
        int t = base_t + tid;
        bs[tid] = (t >= 0) ? beta[(size_t)(b * S_ + t) * H_ + h] : 0.f;
    }
    __syncthreads();

    for (int i = tid; i < ATT_ROWS * 16; i += 256) {
        int r = i >> 4;
        int c = (i & 15) * 4;
        int t = base_t + r;
        if (t < 0) continue;
        float4 a = *(float4*)&ks[r * DH_ + c];
        float4 p = *(float4*)&ks[r * DH_ + c + 64];
        float4 ct4 = *(const float4*)&ctab[(size_t)t * 64 + c];
        float4 st4 = *(const float4*)&stab[(size_t)t * 64 + c];
        float4 lo, hi;
        lo.x = a.x*ct4.x - p.x*st4.x;  hi.x = p.x*ct4.x + a.x*st4.x;
        lo.y = a.y*ct4.y - p.y*st4.y;  hi.y = p.y*ct4.y + a.y*st4.y;
        lo.z = a.z*ct4.z - p.z*st4.z;  hi.z = p.z*ct4.z + a.z*st4.z;
        lo.w = a.w*ct4.w - p.w*st4.w;  hi.w = p.w*ct4.w + a.w*st4.w;
        *(float4*)&ks[r * DH_ + c]      = lo;
        *(float4*)&ks[r * DH_ + c + 64] = hi;
    }
    __syncthreads();

    int sA = s0 + 2 * wid;
    int sB = sA + 1;
    float am = g_amean[h];
    float am2 = am * am;
    float am3 = am2 * am;
    float am4 = am2 * am2;
    int c4 = lane * 4;
    int jj = (lane & 15) * 4;

    float4 qA, qB;
    {
        float4 qraw = *(const float4*)(q + bh + (size_t)sA * INNER_ + c4);
        float4 ct4 = *(const float4*)&ctab[(size_t)sA * 64 + jj];
        float4 st4 = *(const float4*)&stab[(size_t)sA * 64 + jj];
        float px = __shfl_xor_sync(0xffffffffu, qraw.x, 16);
        float py = __shfl_xor_sync(0xffffffffu, qraw.y, 16);
        float pz = __shfl_xor_sync(0xffffffffu, qraw.z, 16);
        float pw = __shfl_xor_sync(0xffffffffu, qraw.w, 16);
        if (lane < 16) {
            qA.x = qraw.x*ct4.x - px*st4.x;
            qA.y = qraw.y*ct4.y - py*st4.y;
            qA.z = qraw.z*ct4.z - pz*st4.z;
            qA.w = qraw.w*ct4.w - pw*st4.w;
        } else {
            qA.x = qraw.x*ct4.x + px*st4.x;
            qA.y = qraw.y*ct4.y + py*st4.y;
            qA.z = qraw.z*ct4.z + pz*st4.z;
            qA.w = qraw.w*ct4.w + pw*st4.w;
        }
    }
    {
        float4 qraw = *(const float4*)(q + bh + (size_t)sB * INNER_ + c4);
        float4 ct4 = *(const float4*)&ctab[(size_t)sB * 64 + jj];
        float4 st4 = *(const float4*)&stab[(size_t)sB * 64 + jj];
        float px = __shfl_xor_sync(0xffffffffu, qraw.x, 16);
        float py = __shfl_xor_sync(0xffffffffu, qraw.y, 16);
        float pz = __shfl_xor_sync(0xffffffffu, qraw.z, 16);
        float pw = __shfl_xor_sync(0xffffffffu, qraw.w, 16);
        if (lane < 16) {
            qB.x = qraw.x*ct4.x - px*st4.x;
            qB.y = qraw.y*ct4.y - py*st4.y;
            qB.z = qraw.z*ct4.z - pz*st4.z;
            qB.w = qraw.w*ct4.w - pw*st4.w;
        } else {
            qB.x = qraw.x*ct4.x + px*st4.x;
            qB.y = qraw.y*ct4.y + py*st4.y;
            qB.z = qraw.z*ct4.z + pz*st4.z;
            qB.w = qraw.w*ct4.w + pw*st4.w;
        }
    }

    float4 accA = make_float4(0.f, 0.f, 0.f, 0.f);
    float4 accB = make_float4(0.f, 0.f, 0.f, 0.f);
    int rB = sB - base_t;

    {
        float4 k0 = *(const float4*)&ks[rB * DH_ + c4];
        float4 v0 = *(const float4*)&vs[rB * DH_ + c4];
        float d = qB.x*k0.x + qB.y*k0.y + qB.z*k0.z + qB.w*k0.w;
        #pragma unroll
        for (int o = 16; o; o >>= 1) d += __shfl_xor_sync(0xffffffffu, d, o);
        float w = d * bs[rB];
        accB.x = fmaf(w, v0.x, accB.x);
        accB.y = fmaf(w, v0.y, accB.y);
        accB.z = fmaf(w, v0.z, accB.z);
        accB.w = fmaf(w, v0.w, accB.w);
    }

    float decayA = 1.f;
    #pragma unroll
    for (int g = 0; g < 8; ++g) {
        int r0 = rB - 1 - 4 * g;
        float4 k0 = *(const float4*)&ks[(r0  ) * DH_ + c4];
        float4 v0 = *(const float4*)&vs[(r0  ) * DH_ + c4];
        float4 k1 = *(const float4*)&ks[(r0-1) * DH_ + c4];
        float4 v1 = *(const float4*)&vs[(r0-1) * DH_ + c4];
        float4 k2 = *(const float4*)&ks[(r0-2) * DH_ + c4];
        float4 v2 = *(const float4*)&vs[(r0-2) * DH_ + c4];
        float4 k3 = *(const float4*)&ks[(r0-3) * DH_ + c4];
        float4 v3 = *(const float4*)&vs[(r0-3) * DH_ + c4];
        float dA0 = qA.x*k0.x + qA.y*k0.y + qA.z*k0.z + qA.w*k0.w;
        float dB0 = qB.x*k0.x + qB.y*k0.y + qB.z*k0.z + qB.w*k0.w;
        float dA1 = qA.x*k1.x + qA.y*k1.y + qA.z*k1.z + qA.w*k1.w;
        float dB1 = qB.x*k1.x + qB.y*k1.y + qB.z*k1.z + qB.w*k1.w;
        float dA2 = qA.x*k2.x + qA.y*k2.y + qA.z*k2.z + qA.w*k2.w;
        float dB2 = qB.x*k2.x + qB.y*k2.y + qB.z*k2.z + qB.w*k2.w;
        float dA3 = qA.x*k3.x + qA.y*k3.y + qA.z*k3.z + qA.w*k3.w;
        float dB3 = qB.x*k3.x + qB.y*k3.y + qB.z*k3.z + qB.w*k3.w;
        #pragma unroll
        for (int o = 16; o; o >>= 1) {
            dA0 += __shfl_xor_sync(0xffffffffu, dA0, o);
            dB0 += __shfl_xor_sync(0xffffffffu, dB0, o);
            dA1 += __shfl_xor_sync(0xffffffffu, dA1, o);
            dB1 += __shfl_xor_sync(0xffffffffu, dB1, o);
            dA2 += __shfl_xor_sync(0xffffffffu, dA2, o);
            dB2 += __shfl_xor_sync(0xffffffffu, dB2, o);
            dA3 += __shfl_xor_sync(0xffffffffu, dA3, o);
            dB3 += __shfl_xor_sync(0xffffffffu, dB3, o);
        }
        float b0 = bs[r0], b1 = bs[r0-1], b2 = bs[r0-2], b3 = bs[r0-3];
        float wA0 = dA0 * decayA * b0;
        float wA1 = dA1 * decayA * am  * b1;
        float wA2 = dA2 * decayA * am2 * b2;
        float wA3 = dA3 * decayA * am3 * b3;
        float wB0 = dB0 * decayA * am  * b0;
        float wB1 = dB1 * decayA * am2 * b1;
        float wB2 = dB2 * decayA * am3 * b2;
        float wB3 = (g < 7) ? dB3 * decayA * am4 * b3 : 0.f;
        accA.x = fmaf(wA0, v0.x, fmaf(wA1, v1.x, fmaf(wA2, v2.x, fmaf(wA3, v3.x, accA.x))));
        accA.y = fmaf(wA0, v0.y, fmaf(wA1, v1.y, fmaf(wA2, v2.y, fmaf(wA3, v3.y, accA.y))));
        accA.z = fmaf(wA0, v0.z, fmaf(wA1, v1.z, fmaf(wA2, v2.z, fmaf(wA3, v3.z, accA.z))));
        accA.w = fmaf(wA0, v0.w, fmaf(wA1, v1.w, fmaf(wA2, v2.w, fmaf(wA3, v3.w, accA.w))));
        accB.x = fmaf(wB0, v0.x, fmaf(wB1, v1.x, fmaf(wB2, v2.x, fmaf(wB3, v3.x, accB.x))));
        accB.y = fmaf(wB0, v0.y, fmaf(wB1, v1.y, fmaf(wB2, v2.y, fmaf(wB3, v3.y, accB.y))));
        accB.z = fmaf(wB0, v0.z, fmaf(wB1, v1.z, fmaf(wB2, v2.z, fmaf(wB3, v3.z, accB.z))));
        accB.w = fmaf(wB0, v0.w, fmaf(wB1, v1.w, fmaf(wB2, v2.w, fmaf(wB3, v3.w, accB.w))));
        decayA *= am4;
    }

    size_t oA = bh + (size_t)sA * INNER_ + c4;
    size_t oB = bh + (size_t)sB * INNER_ + c4;
    ((__half2*)(ah + oA))[0] = __half2(__float2half(accA.x), __float2half(accA.y));
    ((__half2*)(ah + oA))[1] = __half2(__float2half(accA.z), __float2half(accA.w));
    ((__half2*)(ah + oB))[0] = __half2(__float2half(accB.x), __float2half(accB.y));
    ((__half2*)(ah + oB))[1] = __half2(__float2half(accB.z), __float2half(accB.w));
}

// ---------------- recurrent state: partial chunks + combine ----------------
__global__ __launch_bounds__(256) void state_part(const float* __restrict__ k,
                                                  const float* __restrict__ v,
                                                  const float* __restrict__ beta,
                                                  const float* __restrict__ alpha_log,
                                                  const float* __restrict__ ctab,
                                                  const float* __restrict__ stab,
                                                  float* __restrict__ part,
                                                  int b) {
    int h  = blockIdx.x >> 2;
    int c  = blockIdx.x & 3;
    int bh = b * H_ + h;
    int tid = threadIdx.x;
    int d = tid >> 1;
    int e0 = (tid & 1) * 64;
    __shared__ float ks[DH_], vs[DH_];
    float st[64];
    #pragma unroll
    for (int e = 0; e < 64; e++) st[e] = 0.f;
    float ad = sigmoidf_(alpha_log[h * DH_ + d]);
    int tbeg = S_ - STWIN_ + c * STLEN;
    for (int t = tbeg; t < tbeg + STLEN; t++) {
        __syncthreads();
        size_t base = (size_t)(b * S_ + t) * INNER_ + h * DH_;
        if (tid < 128) ks[tid] = k[base + tid];
        else           vs[tid - 128] = v[base + tid - 128];
        __syncthreads();
        float cv = ctab[(size_t)t * 64 + (d & 63)];
        float sv = stab[(size_t)t * 64 + (d & 63)];
        float kd = (d < 64) ? ks[d] * cv - ks[d + 64] * sv
                            : ks[d] * cv + ks[d - 64] * sv;
        float kb = kd * beta[(b * S_ + t) * H_ + h];
        #pragma unroll
        for (int e = 0; e < 64; e++)
            st[e] = fmaf(ad, st[e], kb * vs[e0 + e]);
    }
    float* op = part + (((size_t)bh * STCH + c) * DH_ + d) * DH_ + e0;
    #pragma unroll
    for (int e = 0; e < 64; e++) op[e] = st[e];
}

__global__ __launch_bounds__(256) void state_comb(const float* __restrict__ part,
                                                  const float* __restrict__ alpha_log,
                                                  float* __restrict__ stout) {
    int bh = blockIdx.x;
    int h = bh & 7;
    int tid = threadIdx.x;
    int d = tid >> 1;
    int e0 = (tid & 1) * 64;
    float ad = sigmoidf_(alpha_log[h * DH_ + d]);
    float a32 = ad;
    a32 *= a32; a32 *= a32; a32 *= a32; a32 *= a32; a32 *= a32;
    const float* p0 = part + (((size_t)bh * STCH + 0) * DH_ + d) * DH_ + e0;
    const float* p1 = part + (((size_t)bh * STCH + 1) * DH_ + d) * DH_ + e0;
    const float* p2 = part + (((size_t)bh * STCH + 2) * DH_ + d) * DH_ + e0;
    const float* p3 = part + (((size_t)bh * STCH + 3) * DH_ + d) * DH_ + e0;
    float* op = stout + ((size_t)bh * DH_ + d) * DH_ + e0;
    #pragma unroll
    for (int e = 0; e < 64; e++) {
        float r = p0[e];
        r = fmaf(r, a32, p1[e]);
        r = fmaf(r, a32, p2[e]);
        r = fmaf(r, a32, p3[e]);
        op[e] = r;
    }
}

// ---------------- launch ----------------
extern "C" void kernel_launch(void* const* d_in, const int* in_sizes, int n_in,
                              void* d_out, int out_size) {
    const float* x         = (const float*)d_in[0];
    const float* Wq        = (const float*)d_in[1];
    const float* Wk        = (const float*)d_in[2];
    const float* Wv        = (const float*)d_in[3];
    const float* Wo        = (const float*)d_in[4];
    const float* Wb        = (const float*)d_in[5];
    const float* bb        = (const float*)d_in[6];
    const float* alpha_log = (const float*)d_in[7];
    float* out = (float*)d_out;

    float *q, *k, *v, *beta, *stpart, *ctab, *stab;
    cudaGetSymbolAddress((void**)&q,      g_q);
    cudaGetSymbolAddress((void**)&k,      g_k);
    cudaGetSymbolAddress((void**)&v,      g_v);
    cudaGetSymbolAddress((void**)&beta,   g_beta);
    cudaGetSymbolAddress((void**)&stpart, g_stpart);
    cudaGetSymbolAddress((void**)&ctab,   g_ctab);
    cudaGetSymbolAddress((void**)&stab,   g_stab);
    __half *xh, *wqh, *wkh, *wvh, *woh, *ah;
    cudaGetSymbolAddress((void**)&xh,  g_xh);
    cudaGetSymbolAddress((void**)&wqh, g_wqh);
    cudaGetSymbolAddress((void**)&wkh, g_wkh);
    cudaGetSymbolAddress((void**)&wvh, g_wvh);
    cudaGetSymbolAddress((void**)&woh, g_woh);
    cudaGetSymbolAddress((void**)&ah,  g_ah);

    // one-time resources (host-side handles, no device memory)
    static cudaStream_t s1 = 0, s2 = 0;
    static cudaEvent_t ePm, eQ0, eQ1, eA0a, eA0b, eA1a, eA1b, eS, eO;
    if (!s1) {
        cudaStreamCreateWithFlags(&s1, cudaStreamNonBlocking);
        cudaStreamCreateWithFlags(&s2, cudaStreamNonBlocking);
        cudaEventCreateWithFlags(&ePm,  cudaEventDisableTiming);
        cudaEventCreateWithFlags(&eQ0,  cudaEventDisableTiming);
        cudaEventCreateWithFlags(&eQ1,  cudaEventDisableTiming);
        cudaEventCreateWithFlags(&eA0a, cudaEventDisableTiming);
        cudaEventCreateWithFlags(&eA0b, cudaEventDisableTiming);
        cudaEventCreateWithFlags(&eA1a, cudaEventDisableTiming);
        cudaEventCreateWithFlags(&eA1b, cudaEventDisableTiming);
        cudaEventCreateWithFlags(&eS,   cudaEventDisableTiming);
        cudaEventCreateWithFlags(&eO,   cudaEventDisableTiming);
        cudaFuncSetAttribute(hmma_gemm, cudaFuncAttributeMaxDynamicSharedMemorySize, GEMM_SMEM);
    }

    // ---- prep: main-stream (xh + weights) ∥ side-stream (beta/rope/amean) --
    prep_main<<<16384, 256>>>(x, Wq, Wk, Wv, Wo, xh, wqh, wkh, wvh, woh);
    cudaEventRecord(ePm, 0);
    prep_side<<<PS_GRID, 256, 0, s1>>>(x, Wb, bb, alpha_log, beta, ctab, stab);

    // ---- QKV GEMMs: batch0 on main, batch1 on s2 (back-fill) ----
    dim3 gqkv(INNER_/128, SROWS/128, 3);
    hmma_gemm<<<gqkv, 256, GEMM_SMEM>>>(xh, wqh, wkh, wvh, q, k, v, DM_, INNER_, 0);
    cudaEventRecord(eQ0, 0);
    cudaStreamWaitEvent(s2, ePm, 0);
    hmma_gemm<<<gqkv, 256, GEMM_SMEM, s2>>>(xh, wqh, wkh, wvh, q, k, v, DM_, INNER_, SROWS);
    cudaEventRecord(eQ1, s2);

    // ---- side stream: attention (half-batch chunks) + state ----
    dim3 gattn(HROWS/ATT_S, H_, 1);
    cudaStreamWaitEvent(s1, eQ0, 0);
    attn_kernel<<<gattn, 256, 0, s1>>>(q, k, v, beta, ctab, stab, ah, 0, 0);
    cudaEventRecord(eA0a, s1);
    attn_kernel<<<gattn, 256, 0, s1>>>(q, k, v, beta, ctab, stab, ah, 0, HROWS);
    cudaEventRecord(eA0b, s1);
    state_part<<<H_ * STCH, 256, 0, s1>>>(k, v, beta, alpha_log, ctab, stab, stpart, 0);
    cudaStreamWaitEvent(s1, eQ1, 0);
    attn_kernel<<<gattn, 256, 0, s1>>>(q, k, v, beta, ctab, stab, ah, 1, 0);
    cudaEventRecord(eA1a, s1);
    attn_kernel<<<gattn, 256, 0, s1>>>(q, k, v, beta, ctab, stab, ah, 1, HROWS);
    cudaEventRecord(eA1b, s1);
    state_part<<<H_ * STCH, 256, 0, s1>>>(k, v, beta, alpha_log, ctab, stab, stpart, 1);
    state_comb<<<B_ * H_, 256, 0, s1>>>(stpart, alpha_log, out + (size_t)MROWS * DM_);
    cudaEventRecord(eS, s1);

    // ---- O-proj GEMMs: chunks alternate between main stream and s2 ----
    dim3 gout(DM_/128, HROWS/128, 1);
    cudaStreamWaitEvent(0, eA0a, 0);
    hmma_gemm<<<gout, 256, GEMM_SMEM>>>(ah, woh, woh, woh, out, out, out, INNER_, DM_, 0);
    cudaStreamWaitEvent(s2, eA0b, 0);
    hmma_gemm<<<gout, 256, GEMM_SMEM, s2>>>(ah, woh, woh, woh, out, out, out, INNER_, DM_, HROWS);
    cudaStreamWaitEvent(0, eA1a, 0);
    hmma_gemm<<<gout, 256, GEMM_SMEM>>>(ah, woh, woh, woh, out, out, out, INNER_, DM_, SROWS);
    cudaStreamWaitEvent(s2, eA1b, 0);
    hmma_gemm<<<gout, 256, GEMM_SMEM, s2>>>(ah, woh, woh, woh, out, out, out, INNER_, DM_, SROWS + HROWS);
    cudaEventRecord(eO, s2);

    // ---- join side streams back ----
    cudaStreamWaitEvent(0, eO, 0);
    cudaStreamWaitEvent(0, eS, 0);
}